// round 11
// baseline (speedup 1.0000x reference)
#include <cuda_runtime.h>
#include <cuda_fp16.h>
#include <cstdint>

#define DD 128
#define MAX_R 8
#define MAX_N 50000
#define NG 9           // 8 relations + self (W0)

// ---------------- device scratch (no allocs allowed) ----------------
__device__ __half g_agg[(size_t)MAX_R * MAX_N * DD];    // pre-scaled per-(rel,dst) sums, 102.4 MB
__device__ __half g_x16[(size_t)MAX_N * DD];            // fp16 X, 12.8 MB (L2-resident)
__device__ __half g_wh [(size_t)NG * DD * DD];          // fp16 W^T, [g][n][k]

__device__ __forceinline__ uint32_t smem_u32(const void* p) {
    uint32_t a;
    asm("{ .reg .u64 t; cvta.to.shared.u64 t, %1; cvt.u32.u64 %0, t; }" : "=r"(a) : "l"(p));
    return a;
}

// ---------------- fused prep: zero agg + fp16(X) + fp16(W^T) ----------------
// zero items are 32B each (2 consecutive uint4) for write ILP.
#define ZA ((int)((size_t)MAX_R * MAX_N * DD / 16))     // 3,200,000 x 32B zero items
#define XC (MAX_N * DD / 8)                             // 800,000 x-convert items (8 floats each)
#define WC (NG * DD * DD)                               // 147,456 w-convert scalars
__global__ void prep_kernel(const float* __restrict__ X,
                            const float* __restrict__ W,
                            const float* __restrict__ W0)
{
    int i = blockIdx.x * blockDim.x + threadIdx.x;
    if (i < ZA) {
        uint4 z = make_uint4(0, 0, 0, 0);
        ((uint4*)g_agg)[(size_t)i * 2]     = z;
        ((uint4*)g_agg)[(size_t)i * 2 + 1] = z;
    } else if (i < ZA + XC) {
        int j = i - ZA;                                  // 8 floats -> 8 halves (one uint4)
        float4 f0 = ((const float4*)X)[j * 2];
        float4 f1 = ((const float4*)X)[j * 2 + 1];
        uint4 o;
        *(__half2*)&o.x = __floats2half2_rn(f0.x, f0.y);
        *(__half2*)&o.y = __floats2half2_rn(f0.z, f0.w);
        *(__half2*)&o.z = __floats2half2_rn(f1.x, f1.y);
        *(__half2*)&o.w = __floats2half2_rn(f1.z, f1.w);
        ((uint4*)g_x16)[j] = o;
    } else if (i < ZA + XC + WC) {
        int j = i - ZA - XC;
        int g = j / (DD * DD);
        int rem = j - g * DD * DD;
        int n = rem >> 7, k = rem & 127;                 // dest layout [g][n][k]
        float w = (g < MAX_R) ? W[(size_t)g * DD * DD + (size_t)k * DD + n]
                              : W0[(size_t)k * DD + n];
        g_wh[j] = __float2half_rn(w);
    }
}

// ---------------- edge scatter: agg[r,dst] += inv_norm[r,dst] * X16[src] ----------------
// Half-warp per edge, 4 edges batched per half-warp (MLP=4 on L2-resident gathers).
#define EPH 4
__global__ void scatter_kernel(const int* __restrict__ esrc,
                               const int* __restrict__ edst,
                               const int* __restrict__ erel,
                               const float* __restrict__ inv_norm,
                               int E, int N)
{
    int warp = blockIdx.x * (blockDim.x >> 5) + (threadIdx.x >> 5);
    int lane = threadIdx.x & 31;
    int h = lane >> 4;              // half-warp id
    int half = lane & 15;
    int e0 = warp * (2 * EPH);

    uint4 v[EPH];
    __half2 s2[EPH];
    long long off[EPH];
    #pragma unroll
    for (int i = 0; i < EPH; ++i) {
        int e = e0 + i * 2 + h;
        if (e < E) {
            int s = __ldg(&esrc[e]);
            int d = __ldg(&edst[e]);
            int r = __ldg(&erel[e]);
            float sc = __ldg(&inv_norm[(size_t)r * N + d]);
            s2[i] = __float2half2_rn(sc);
            v[i]  = __ldg((const uint4*)(g_x16 + (size_t)s * DD) + half);
            off[i] = ((long long)r * N + d) * DD + half * 8;
        } else off[i] = -1;
    }
    #pragma unroll
    for (int i = 0; i < EPH; ++i) {
        if (off[i] >= 0) {
            uint4 av = v[i];
            *(__half2*)&av.x = __hmul2(*(__half2*)&av.x, s2[i]);
            *(__half2*)&av.y = __hmul2(*(__half2*)&av.y, s2[i]);
            *(__half2*)&av.z = __hmul2(*(__half2*)&av.z, s2[i]);
            *(__half2*)&av.w = __hmul2(*(__half2*)&av.w, s2[i]);
            asm volatile("red.global.add.noftz.v4.f16x2 [%0], {%1, %2, %3, %4};"
                         :: "l"(g_agg + off[i]), "r"(av.x), "r"(av.y), "r"(av.z), "r"(av.w)
                         : "memory");
        }
    }
}

// ---------------- GEMM: out = X@W0 + sum_r agg_r @ W_r  (agg pre-scaled) ----------------
// 512 threads (16 warps = 4/SMSP), warp tile 32x32, cp.async 2-stage pipeline.
#define STAGE_BYTES 65536
#define SMEM_TOTAL  131072

__device__ __forceinline__ void cp16(uint32_t dst, const void* src, int bytes) {
    asm volatile("cp.async.cg.shared.global [%0], [%1], 16, %2;"
                 :: "r"(dst), "l"(src), "r"(bytes) : "memory");
}
#define CP_COMMIT() asm volatile("cp.async.commit_group;" ::: "memory")
#define CP_WAIT(n)  asm volatile("cp.async.wait_group %0;" :: "n"(n) : "memory")

__device__ __forceinline__ void ldmx4(uint32_t* r, uint32_t addr) {
    asm volatile("ldmatrix.sync.aligned.m8n8.x4.shared.b16 {%0,%1,%2,%3}, [%4];"
                 : "=r"(r[0]), "=r"(r[1]), "=r"(r[2]), "=r"(r[3]) : "r"(addr));
}
__device__ __forceinline__ void mma16816h(float* c, const uint32_t* a,
                                          uint32_t b0, uint32_t b1) {
    asm volatile("mma.sync.aligned.m16n8k16.row.col.f32.f16.f16.f32 "
                 "{%0,%1,%2,%3}, {%4,%5,%6,%7}, {%8,%9}, {%0,%1,%2,%3};"
                 : "+f"(c[0]), "+f"(c[1]), "+f"(c[2]), "+f"(c[3])
                 : "r"(a[0]), "r"(a[1]), "r"(a[2]), "r"(a[3]), "r"(b0), "r"(b1));
}

__global__ __launch_bounds__(512, 1)
void gemm_fused_kernel(float* __restrict__ out, int N)
{
    extern __shared__ char smem[];
    uint32_t sb = smem_u32(smem);
    const int t = threadIdx.x, ln = t & 31, wid = t >> 5;
    const int row0 = blockIdx.x * 128;

    // loader geometry: 16B chunk per thread, rows stride 32 (4 iters)
    const int kb  = (t & 15) * 16;           // byte offset in 256B row
    const int col = kb >> 1;                 // half index
    const int rbase = t >> 4;                // row 0..31

    auto issue = [&](int g, int buf) {
        const __half* A = (g < MAX_R) ? (g_agg + (size_t)g * (size_t)N * DD) : g_x16;
        const __half* B = g_wh + (size_t)g * DD * DD;
        uint32_t aBuf = sb + buf * STAGE_BYTES;
        uint32_t bBuf = aBuf + 32768;
        #pragma unroll
        for (int it = 0; it < 4; ++it) {
            int row = rbase + it * 32;
            int gr = row0 + row;
            uint32_t dst = (uint32_t)(row * 256 + (kb ^ ((row & 7) << 4)));
            int ok = (gr < N);
            const __half* ap = A + (size_t)(ok ? gr : 0) * DD + col;
            cp16(aBuf + dst, ap, ok ? 16 : 0);           // zero-fill tail rows
            cp16(bBuf + dst, B + (size_t)row * DD + col, 16);
        }
    };

    float c[2][4][4];
    #pragma unroll
    for (int mi = 0; mi < 2; ++mi)
        #pragma unroll
        for (int j = 0; j < 4; ++j)
            #pragma unroll
            for (int q = 0; q < 4; ++q) c[mi][j][q] = 0.f;

    const int m0 = (wid & 3) * 32;     // 4 M-warps
    const int n0 = (wid >> 2) * 32;    // 4 N-warps
    const int rA   = ln & 15;
    const int koff = ln & 16;

    issue(0, 0); CP_COMMIT();
    issue(1, 1); CP_COMMIT();

    for (int g = 0; g < NG; ++g) {
        if (g < NG - 1) { CP_WAIT(1); } else { CP_WAIT(0); }   // stage g resident
        __syncthreads();

        uint32_t aBase = sb + (g & 1) * STAGE_BYTES;
        uint32_t bBase = aBase + 32768;
        #pragma unroll
        for (int ks = 0; ks < 8; ++ks) {
            int kbb = ks * 32;
            uint32_t ah[8], b[8];
            #pragma unroll
            for (int mi = 0; mi < 2; ++mi) {
                int r = m0 + mi * 16 + rA;
                ldmx4(ah + mi * 4, aBase + r * 256 + ((kbb + koff) ^ ((r & 7) << 4)));
            }
            #pragma unroll
            for (int j2 = 0; j2 < 2; ++j2) {
                int r = n0 + j2 * 16 + rA;
                ldmx4(b + j2 * 4, bBase + r * 256 + ((kbb + koff) ^ ((r & 7) << 4)));
            }
            #pragma unroll
            for (int mi = 0; mi < 2; ++mi)
                #pragma unroll
                for (int j2 = 0; j2 < 2; ++j2) {
                    mma16816h(c[mi][2 * j2],     ah + mi * 4, b[j2 * 4 + 0], b[j2 * 4 + 2]);
                    mma16816h(c[mi][2 * j2 + 1], ah + mi * 4, b[j2 * 4 + 1], b[j2 * 4 + 3]);
                }
        }
        __syncthreads();                                   // readers done with stage g
        if (g + 2 < NG) { issue(g + 2, g & 1); CP_COMMIT(); }
    }

    // epilogue: fp32 result -> out
    #pragma unroll
    for (int mi = 0; mi < 2; ++mi) {
        int r0 = row0 + m0 + mi * 16 + (ln >> 2);
        #pragma unroll
        for (int j = 0; j < 4; ++j) {
            int colo = n0 + j * 8 + (ln & 3) * 2;
            if (r0 < N)
                *(float2*)(out + (size_t)r0 * DD + colo) = make_float2(c[mi][j][0], c[mi][j][1]);
            if (r0 + 8 < N)
                *(float2*)(out + (size_t)(r0 + 8) * DD + colo) = make_float2(c[mi][j][2], c[mi][j][3]);
        }
    }
}

extern "C" void kernel_launch(void* const* d_in, const int* in_sizes, int n_in,
                              void* d_out, int out_size)
{
    const float* X        = (const float*)d_in[0];
    const float* W        = (const float*)d_in[1];
    const float* W0       = (const float*)d_in[2];
    const float* inv_norm = (const float*)d_in[3];
    const int*   esrc     = (const int*)d_in[4];
    const int*   edst     = (const int*)d_in[5];
    const int*   erel     = (const int*)d_in[6];
    float* out = (float*)d_out;

    int N = in_sizes[0] / DD;            // 50000
    int E = in_sizes[4];                 // 800000

    // Phase 0: fused prep (zero agg + fp16 X + fp16 W^T)
    int prep_items = ZA + XC + WC;
    prep_kernel<<<(prep_items + 255) / 256, 256>>>(X, W, W0);

    // Phase 1: scatter pre-scaled X rows into agg
    int edges_per_block = (256 / 32) * 2 * EPH;   // 8 warps x 8 edges
    scatter_kernel<<<(E + edges_per_block - 1) / edges_per_block, 256>>>(esrc, edst, erel, inv_norm, E, N);

    // Phase 2: pipelined GEMM — out = X@W0 + sum_r agg_r @ W_r
    cudaFuncSetAttribute(gemm_fused_kernel, cudaFuncAttributeMaxDynamicSharedMemorySize, SMEM_TOTAL);
    gemm_fused_kernel<<<(N + 127) / 128, 512, SMEM_TOTAL>>>(out, N);
}

// round 12
// speedup vs baseline: 1.0469x; 1.0469x over previous
#include <cuda_runtime.h>
#include <cuda_fp16.h>
#include <cstdint>

#define DD 128
#define MAX_R 8
#define MAX_N 50000
#define NG 9           // 8 relations + self (W0)

// ---------------- device scratch (no allocs allowed) ----------------
__device__ __half g_agg[(size_t)MAX_R * MAX_N * DD];    // pre-scaled per-(rel,dst) sums, 102.4 MB
__device__ __half g_x16[(size_t)MAX_N * DD];            // fp16 X, 12.8 MB (L2-resident)
__device__ __half g_wh [(size_t)NG * DD * DD];          // fp16 W^T, [g][n][k]

__device__ __forceinline__ uint32_t smem_u32(const void* p) {
    uint32_t a;
    asm("{ .reg .u64 t; cvta.to.shared.u64 t, %1; cvt.u32.u64 %0, t; }" : "=r"(a) : "l"(p));
    return a;
}

// ---------------- fused prep: zero agg + fp16(X) + fp16(W^T) ----------------
// (round-8 form: one independent 16B store per thread — measured 23.6us)
#define ZA ((int)((size_t)MAX_R * MAX_N * DD / 8))      // 6,400,000 uint4 zero items
#define XC (MAX_N * DD / 8)                             // 800,000 x-convert items (8 floats each)
#define WC (NG * DD * DD)                               // 147,456 w-convert scalars
__global__ void prep_kernel(const float* __restrict__ X,
                            const float* __restrict__ W,
                            const float* __restrict__ W0)
{
    int i = blockIdx.x * blockDim.x + threadIdx.x;
    if (i < ZA) {
        ((uint4*)g_agg)[i] = make_uint4(0, 0, 0, 0);
    } else if (i < ZA + XC) {
        int j = i - ZA;                                  // 8 floats -> 8 halves (one uint4)
        float4 f0 = ((const float4*)X)[j * 2];
        float4 f1 = ((const float4*)X)[j * 2 + 1];
        uint4 o;
        *(__half2*)&o.x = __floats2half2_rn(f0.x, f0.y);
        *(__half2*)&o.y = __floats2half2_rn(f0.z, f0.w);
        *(__half2*)&o.z = __floats2half2_rn(f1.x, f1.y);
        *(__half2*)&o.w = __floats2half2_rn(f1.z, f1.w);
        ((uint4*)g_x16)[j] = o;
    } else if (i < ZA + XC + WC) {
        int j = i - ZA - XC;
        int g = j / (DD * DD);
        int rem = j - g * DD * DD;
        int n = rem >> 7, k = rem & 127;                 // dest layout [g][n][k]
        float w = (g < MAX_R) ? W[(size_t)g * DD * DD + (size_t)k * DD + n]
                              : W0[(size_t)k * DD + n];
        g_wh[j] = __float2half_rn(w);
    }
}

// ---------------- edge scatter: agg[r,dst] += inv_norm[r,dst] * X16[src] ----------------
// Half-warp per edge, 4 edges batched per half-warp (MLP=4 on L2-resident gathers).
#define EPH 4
__global__ void scatter_kernel(const int* __restrict__ esrc,
                               const int* __restrict__ edst,
                               const int* __restrict__ erel,
                               const float* __restrict__ inv_norm,
                               int E, int N)
{
    int warp = blockIdx.x * (blockDim.x >> 5) + (threadIdx.x >> 5);
    int lane = threadIdx.x & 31;
    int h = lane >> 4;              // half-warp id
    int half = lane & 15;
    int e0 = warp * (2 * EPH);

    uint4 v[EPH];
    __half2 s2[EPH];
    long long off[EPH];
    #pragma unroll
    for (int i = 0; i < EPH; ++i) {
        int e = e0 + i * 2 + h;
        if (e < E) {
            int s = __ldg(&esrc[e]);
            int d = __ldg(&edst[e]);
            int r = __ldg(&erel[e]);
            float sc = __ldg(&inv_norm[(size_t)r * N + d]);
            s2[i] = __float2half2_rn(sc);
            v[i]  = __ldg((const uint4*)(g_x16 + (size_t)s * DD) + half);
            off[i] = ((long long)r * N + d) * DD + half * 8;
        } else off[i] = -1;
    }
    #pragma unroll
    for (int i = 0; i < EPH; ++i) {
        if (off[i] >= 0) {
            uint4 av = v[i];
            *(__half2*)&av.x = __hmul2(*(__half2*)&av.x, s2[i]);
            *(__half2*)&av.y = __hmul2(*(__half2*)&av.y, s2[i]);
            *(__half2*)&av.z = __hmul2(*(__half2*)&av.z, s2[i]);
            *(__half2*)&av.w = __hmul2(*(__half2*)&av.w, s2[i]);
            asm volatile("red.global.add.noftz.v4.f16x2 [%0], {%1, %2, %3, %4};"
                         :: "l"(g_agg + off[i]), "r"(av.x), "r"(av.y), "r"(av.z), "r"(av.w)
                         : "memory");
        }
    }
}

// ---------------- GEMM: out = X@W0 + sum_r agg_r @ W_r  (agg pre-scaled) ----------------
// 512 threads, warp tile 32x32, cp.async 3-stage ring (prefetch depth 2).
#define STAGE_BYTES 65536
#define SMEM_TOTAL  (3 * STAGE_BYTES)    // 196608

__device__ __forceinline__ void cp16(uint32_t dst, const void* src, int bytes) {
    asm volatile("cp.async.cg.shared.global [%0], [%1], 16, %2;"
                 :: "r"(dst), "l"(src), "r"(bytes) : "memory");
}
#define CP_COMMIT() asm volatile("cp.async.commit_group;" ::: "memory")
#define CP_WAIT(n)  asm volatile("cp.async.wait_group %0;" :: "n"(n) : "memory")

__device__ __forceinline__ void ldmx4(uint32_t* r, uint32_t addr) {
    asm volatile("ldmatrix.sync.aligned.m8n8.x4.shared.b16 {%0,%1,%2,%3}, [%4];"
                 : "=r"(r[0]), "=r"(r[1]), "=r"(r[2]), "=r"(r[3]) : "r"(addr));
}
__device__ __forceinline__ void mma16816h(float* c, const uint32_t* a,
                                          uint32_t b0, uint32_t b1) {
    asm volatile("mma.sync.aligned.m16n8k16.row.col.f32.f16.f16.f32 "
                 "{%0,%1,%2,%3}, {%4,%5,%6,%7}, {%8,%9}, {%0,%1,%2,%3};"
                 : "+f"(c[0]), "+f"(c[1]), "+f"(c[2]), "+f"(c[3])
                 : "r"(a[0]), "r"(a[1]), "r"(a[2]), "r"(a[3]), "r"(b0), "r"(b1));
}

__global__ __launch_bounds__(512, 1)
void gemm_fused_kernel(float* __restrict__ out, int N)
{
    extern __shared__ char smem[];
    uint32_t sb = smem_u32(smem);
    const int t = threadIdx.x, ln = t & 31, wid = t >> 5;
    const int row0 = blockIdx.x * 128;

    // loader geometry: 16B chunk per thread, rows stride 32 (4 iters)
    const int kb  = (t & 15) * 16;           // byte offset in 256B row
    const int col = kb >> 1;                 // half index
    const int rbase = t >> 4;                // row 0..31

    auto issue = [&](int g, int buf) {
        const __half* A = (g < MAX_R) ? (g_agg + (size_t)g * (size_t)N * DD) : g_x16;
        const __half* B = g_wh + (size_t)g * DD * DD;
        uint32_t aBuf = sb + buf * STAGE_BYTES;
        uint32_t bBuf = aBuf + 32768;
        #pragma unroll
        for (int it = 0; it < 4; ++it) {
            int row = rbase + it * 32;
            int gr = row0 + row;
            uint32_t dst = (uint32_t)(row * 256 + (kb ^ ((row & 7) << 4)));
            int ok = (gr < N);
            const __half* ap = A + (size_t)(ok ? gr : 0) * DD + col;
            cp16(aBuf + dst, ap, ok ? 16 : 0);           // zero-fill tail rows
            cp16(bBuf + dst, B + (size_t)row * DD + col, 16);
        }
    };

    float c[2][4][4];
    #pragma unroll
    for (int mi = 0; mi < 2; ++mi)
        #pragma unroll
        for (int j = 0; j < 4; ++j)
            #pragma unroll
            for (int q = 0; q < 4; ++q) c[mi][j][q] = 0.f;

    const int m0 = (wid & 3) * 32;     // 4 M-warps
    const int n0 = (wid >> 2) * 32;    // 4 N-warps
    const int rA   = ln & 15;
    const int koff = ln & 16;

    issue(0, 0); CP_COMMIT();
    issue(1, 1); CP_COMMIT();
    issue(2, 2); CP_COMMIT();

    for (int g = 0; g < NG; ++g) {
        // stage g resident: leave the still-inflight stages pending
        if (g <= NG - 3)      { CP_WAIT(2); }
        else if (g == NG - 2) { CP_WAIT(1); }
        else                  { CP_WAIT(0); }
        __syncthreads();

        int buf = g % 3;
        uint32_t aBase = sb + buf * STAGE_BYTES;
        uint32_t bBase = aBase + 32768;
        #pragma unroll
        for (int ks = 0; ks < 8; ++ks) {
            int kbb = ks * 32;
            uint32_t ah[8], b[8];
            #pragma unroll
            for (int mi = 0; mi < 2; ++mi) {
                int r = m0 + mi * 16 + rA;
                ldmx4(ah + mi * 4, aBase + r * 256 + ((kbb + koff) ^ ((r & 7) << 4)));
            }
            #pragma unroll
            for (int j2 = 0; j2 < 2; ++j2) {
                int r = n0 + j2 * 16 + rA;
                ldmx4(b + j2 * 4, bBase + r * 256 + ((kbb + koff) ^ ((r & 7) << 4)));
            }
            #pragma unroll
            for (int mi = 0; mi < 2; ++mi)
                #pragma unroll
                for (int j2 = 0; j2 < 2; ++j2) {
                    mma16816h(c[mi][2 * j2],     ah + mi * 4, b[j2 * 4 + 0], b[j2 * 4 + 2]);
                    mma16816h(c[mi][2 * j2 + 1], ah + mi * 4, b[j2 * 4 + 1], b[j2 * 4 + 3]);
                }
        }
        __syncthreads();                                   // readers done with buf
        if (g + 3 < NG) { issue(g + 3, buf); CP_COMMIT(); }
    }

    // epilogue: fp32 result -> out
    #pragma unroll
    for (int mi = 0; mi < 2; ++mi) {
        int r0 = row0 + m0 + mi * 16 + (ln >> 2);
        #pragma unroll
        for (int j = 0; j < 4; ++j) {
            int colo = n0 + j * 8 + (ln & 3) * 2;
            if (r0 < N)
                *(float2*)(out + (size_t)r0 * DD + colo) = make_float2(c[mi][j][0], c[mi][j][1]);
            if (r0 + 8 < N)
                *(float2*)(out + (size_t)(r0 + 8) * DD + colo) = make_float2(c[mi][j][2], c[mi][j][3]);
        }
    }
}

extern "C" void kernel_launch(void* const* d_in, const int* in_sizes, int n_in,
                              void* d_out, int out_size)
{
    const float* X        = (const float*)d_in[0];
    const float* W        = (const float*)d_in[1];
    const float* W0       = (const float*)d_in[2];
    const float* inv_norm = (const float*)d_in[3];
    const int*   esrc     = (const int*)d_in[4];
    const int*   edst     = (const int*)d_in[5];
    const int*   erel     = (const int*)d_in[6];
    float* out = (float*)d_out;

    int N = in_sizes[0] / DD;            // 50000
    int E = in_sizes[4];                 // 800000

    // Phase 0: fused prep (zero agg + fp16 X + fp16 W^T)
    int prep_items = ZA + XC + WC;
    prep_kernel<<<(prep_items + 255) / 256, 256>>>(X, W, W0);

    // Phase 1: scatter pre-scaled X rows into agg
    int edges_per_block = (256 / 32) * 2 * EPH;   // 8 warps x 8 edges
    scatter_kernel<<<(E + edges_per_block - 1) / edges_per_block, 256>>>(esrc, edst, erel, inv_norm, E, N);

    // Phase 2: pipelined GEMM — out = X@W0 + sum_r agg_r @ W_r
    cudaFuncSetAttribute(gemm_fused_kernel, cudaFuncAttributeMaxDynamicSharedMemorySize, SMEM_TOTAL);
    gemm_fused_kernel<<<(N + 127) / 128, 512, SMEM_TOTAL>>>(out, N);
}